// round 15
// baseline (speedup 1.0000x reference)
#include <cuda_runtime.h>
#include <cuda_fp16.h>
#include <math.h>
#include <stdint.h>

#define TSEQ   2048
#define BATCH  2
#define CDIM   1024
#define NHEAD  16
#define HD     64
#define WIN    256
#define MROWS  (BATCH*TSEQ)   /* 4096 */

// Scratch (allocation-free rule: __device__ globals; uint16 = half storage)
static __device__ unsigned short g_q[(size_t)MROWS*CDIM];
static __device__ unsigned short g_k[(size_t)MROWS*CDIM];
static __device__ unsigned short g_v[(size_t)MROWS*CDIM];
static __device__ unsigned short g_y[(size_t)MROWS*CDIM];
static __device__ unsigned short g_xh[(size_t)MROWS*CDIM];
static __device__ unsigned short g_wh[4][(size_t)CDIM*CDIM];

// ===========================================================================
// PTX helpers
// ===========================================================================
__device__ __forceinline__ uint32_t smem_u32(const void* p) {
    uint32_t a;
    asm("{ .reg .u64 t; cvta.to.shared.u64 t, %1; cvt.u32.u64 %0, t; }" : "=r"(a) : "l"(p));
    return a;
}
__device__ __forceinline__ void cp_async16(uint32_t s, const void* g) {
    asm volatile("cp.async.cg.shared.global [%0], [%1], 16;" :: "r"(s), "l"(g) : "memory");
}
__device__ __forceinline__ void cp_commit() {
    asm volatile("cp.async.commit_group;" ::: "memory");
}
template <int N_>
__device__ __forceinline__ void cp_wait() {
    asm volatile("cp.async.wait_group %0;" :: "n"(N_) : "memory");
}
__device__ __forceinline__ void mma_f16(float* c, const uint32_t* a, const uint32_t* b) {
    asm volatile(
        "mma.sync.aligned.m16n8k16.row.col.f32.f16.f16.f32 "
        "{%0,%1,%2,%3}, {%4,%5,%6,%7}, {%8,%9}, {%0,%1,%2,%3};"
        : "+f"(c[0]), "+f"(c[1]), "+f"(c[2]), "+f"(c[3])
        : "r"(a[0]), "r"(a[1]), "r"(a[2]), "r"(a[3]), "r"(b[0]), "r"(b[1]));
}
__device__ __forceinline__ void ldmatrix_x4(uint32_t& r0, uint32_t& r1,
                                            uint32_t& r2, uint32_t& r3, uint32_t addr) {
    asm volatile("ldmatrix.sync.aligned.m8n8.x4.shared.b16 {%0,%1,%2,%3}, [%4];"
                 : "=r"(r0), "=r"(r1), "=r"(r2), "=r"(r3) : "r"(addr));
}
__device__ __forceinline__ void ldmatrix_x4t(uint32_t& r0, uint32_t& r1,
                                             uint32_t& r2, uint32_t& r3, uint32_t addr) {
    asm volatile("ldmatrix.sync.aligned.m8n8.x4.trans.shared.b16 {%0,%1,%2,%3}, [%4];"
                 : "=r"(r0), "=r"(r1), "=r"(r2), "=r"(r3) : "r"(addr));
}
__device__ __forceinline__ uint32_t packh2(float a, float b) {
    half2 h = __floats2half2_rn(a, b);
    return *(uint32_t*)&h;
}

// ===========================================================================
// Fused prepass: float -> half for X and all 4 weights, one launch.
// ===========================================================================
#define NX4 (MROWS * CDIM / 4)
#define NW4 (CDIM * CDIM / 4)

__global__ void cvt_all_kernel(const float* __restrict__ x,
                               const float* __restrict__ w0, const float* __restrict__ w1,
                               const float* __restrict__ w2, const float* __restrict__ w3,
                               __half* __restrict__ xh, __half* __restrict__ wh)
{
    int i = blockIdx.x * blockDim.x + threadIdx.x;
    const float* src;
    __half* dst;
    int off;
    if (i < NX4) {
        src = x; dst = xh; off = i;
    } else {
        int j = i - NX4;
        int m = j / NW4;
        off = j - m * NW4;
        src = (m == 0) ? w0 : (m == 1) ? w1 : (m == 2) ? w2 : w3;
        dst = wh + (size_t)m * CDIM * CDIM;
    }
    float4 v = ((const float4*)src)[off];
    ((half2*)dst)[2 * off]     = __floats2half2_rn(v.x, v.y);
    ((half2*)dst)[2 * off + 1] = __floats2half2_rn(v.z, v.w);
}

// ===========================================================================
// fp16 mma GEMM core (R12 config — at the legacy-HMMA throughput floor).
// oscale multiplies the (x@W + b) output (used to fold softmax scale into Q).
// ===========================================================================
#define BM 128
#define BN 128
#define BKH 64
#define NSTG 3
#define ASTRH 72
#define BSTRH 136
#define ABYTES (BM * ASTRH * 2)
#define BBYTES (BKH * BSTRH * 2)
#define STAGEB (ABYTES + BBYTES)
#define GEMM_SMEM (NSTG * STAGEB)

__device__ __forceinline__ void gemm_core(const __half* __restrict__ X,
                                          const __half* __restrict__ W,
                                          const float* __restrict__ bias,
                                          float* __restrict__ Yf,
                                          __half* __restrict__ Yh,
                                          int m0, int n0, float oscale, char* dsm)
{
    const int tid  = threadIdx.x;
    const int wid  = tid >> 5;
    const int lane = tid & 31;
    const int wm   = wid & 1;
    const int wn   = wid >> 1;
    const int grp  = lane >> 2;
    const int qid  = lane & 3;

    const uint32_t sbase = smem_u32(dsm);
    uint32_t sAb[NSTG], sBb[NSTG];
#pragma unroll
    for (int s = 0; s < NSTG; s++) {
        sAb[s] = sbase + s * STAGEB;
        sBb[s] = sbase + s * STAGEB + ABYTES;
    }

    float c[4][4][4];
#pragma unroll
    for (int i = 0; i < 4; i++)
#pragma unroll
        for (int j = 0; j < 4; j++)
#pragma unroll
            for (int r = 0; r < 4; r++) c[i][j][r] = 0.f;

    const int a_lrow = (lane & 7) + ((lane >> 3) & 1) * 8;
    const int a_lcol = (lane >> 4) * 8;
    const int b_lcol = (lane >> 4) * 8;
    const int b_lrow = lane & 15;

#define LOAD_STAGE(stg, kk0)                                                       \
    do {                                                                           \
        _Pragma("unroll")                                                          \
        for (int _q = 0; _q < 4; _q++) {                                           \
            int _t = _q * 256 + tid; int _r = _t >> 3, _c = _t & 7;                \
            cp_async16(sAb[(stg)] + (uint32_t)(_r * ASTRH + _c * 8) * 2,           \
                       &X[(size_t)(m0 + _r) * CDIM + (kk0) + _c * 8]);             \
        }                                                                          \
        _Pragma("unroll")                                                          \
        for (int _q = 0; _q < 4; _q++) {                                           \
            int _t = _q * 256 + tid; int _r = _t >> 4, _c = _t & 15;               \
            cp_async16(sBb[(stg)] + (uint32_t)(_r * BSTRH + _c * 8) * 2,           \
                       &W[(size_t)((kk0) + _r) * CDIM + n0 + _c * 8]);             \
        }                                                                          \
    } while (0)

#pragma unroll
    for (int ps = 0; ps < NSTG - 1; ps++) {
        LOAD_STAGE(ps, ps * BKH);
        cp_commit();
    }

    const int NIT = CDIM / BKH;
    for (int kt = 0; kt < NIT; kt++) {
        cp_wait<NSTG - 2>();
        __syncthreads();

        if (kt + NSTG - 1 < NIT)
            LOAD_STAGE((kt + NSTG - 1) % NSTG, (kt + NSTG - 1) * BKH);
        cp_commit();

        const int st = kt % NSTG;
        const uint32_t sAa = sAb[st];
        const uint32_t sBa = sBb[st];
#pragma unroll
        for (int kk = 0; kk < 4; kk++) {
            const int kb = kk * 16;
            uint32_t af[4][4];
#pragma unroll
            for (int i = 0; i < 4; i++) {
                const int row = wm * 64 + i * 16 + a_lrow;
                ldmatrix_x4(af[i][0], af[i][1], af[i][2], af[i][3],
                            sAa + (uint32_t)(row * ASTRH + kb + a_lcol) * 2);
            }
#pragma unroll
            for (int jp = 0; jp < 2; jp++) {
                const int col  = wn * 32 + jp * 16 + b_lcol;
                const int krow = kb + b_lrow;
                uint32_t b0, b1, b2, b3;
                ldmatrix_x4t(b0, b1, b2, b3, sBa + (uint32_t)(krow * BSTRH + col) * 2);
                uint32_t bj0[2] = { b0, b1 };
                uint32_t bj1[2] = { b2, b3 };
#pragma unroll
                for (int i = 0; i < 4; i++) {
                    mma_f16(c[i][jp * 2],     af[i], bj0);
                    mma_f16(c[i][jp * 2 + 1], af[i], bj1);
                }
            }
        }
    }

#pragma unroll
    for (int i = 0; i < 4; i++) {
        const int row = m0 + wm * 64 + i * 16 + grp;
#pragma unroll
        for (int j = 0; j < 4; j++) {
            const int col = n0 + wn * 32 + j * 8 + 2 * qid;
            const float b0 = bias[col], b1 = bias[col + 1];
            const float o0 = (c[i][j][0] + b0) * oscale, o1 = (c[i][j][1] + b1) * oscale;
            const float o2 = (c[i][j][2] + b0) * oscale, o3 = (c[i][j][3] + b1) * oscale;
            if (Yh) {
                *(half2*)&Yh[(size_t)row * CDIM + col]       = __floats2half2_rn(o0, o1);
                *(half2*)&Yh[(size_t)(row + 8) * CDIM + col] = __floats2half2_rn(o2, o3);
            } else {
                float2 v0 = { o0, o1 }, v1 = { o2, o3 };
                *(float2*)&Yf[(size_t)row * CDIM + col]       = v0;
                *(float2*)&Yf[(size_t)(row + 8) * CDIM + col] = v1;
            }
        }
    }
#undef LOAD_STAGE
}

// 0.125 * log2(e): folds the 1/sqrt(64) softmax scale AND the exp->exp2
// conversion into Q at the projection epilogue.
#define QSCALE 0.1803368801111204f

__global__ __launch_bounds__(256, 2)
void gemm_qkv_kernel(const __half* __restrict__ X, const __half* __restrict__ whBase,
                     const float* __restrict__ bq, const float* __restrict__ bk,
                     const float* __restrict__ bv,
                     __half* __restrict__ qo, __half* __restrict__ ko,
                     __half* __restrict__ vo)
{
    extern __shared__ __align__(16) char dsm_g[];
    const int msel = blockIdx.x >> 3;
    const int n0   = (blockIdx.x & 7) * BN;
    const int m0   = blockIdx.y * BM;
    const __half* W = whBase + (size_t)msel * CDIM * CDIM;
    const float* bias = (msel == 0) ? bq : (msel == 1) ? bk : bv;
    __half* Yh = (msel == 0) ? qo : (msel == 1) ? ko : vo;
    const float os = (msel == 0) ? QSCALE : 1.0f;
    gemm_core(X, W, bias, nullptr, Yh, m0, n0, os, dsm_g);
}

__global__ __launch_bounds__(256, 2)
void gemm_out_kernel(const __half* __restrict__ X, const __half* __restrict__ W,
                     const float* __restrict__ bias, float* __restrict__ Yf)
{
    extern __shared__ __align__(16) char dsm_g[];
    gemm_core(X, W, bias, Yf, nullptr, blockIdx.y * BM, blockIdx.x * BN, 1.0f, dsm_g);
}

// ---------------------------------------------------------------------------
// FA2-style sliding-window attention. Q pre-scaled by 0.125*log2e ->
// softmax runs in exp2 domain (bare MUFU.EX2, no multiplies).
// Q fragments hoisted into registers (loop-invariant).
// ---------------------------------------------------------------------------
#define QR     128
#define QSTRH  72
#define KVSTR  72
#define QBYTES (QR * QSTRH * 2)
#define KVTILE (64 * KVSTR * 2)
#define KVSTG  (2 * KVTILE)
#define ANSTG  3
#define ATT_SMEM_B (QBYTES + ANSTG * KVSTG)

__global__ __launch_bounds__(256, 2)
void attn_kernel(const __half* __restrict__ qg, const __half* __restrict__ kg,
                 const __half* __restrict__ vg, __half* __restrict__ yg)
{
    extern __shared__ __align__(16) char dsm[];
    const uint32_t qbase = smem_u32(dsm);
    uint32_t kbase[ANSTG], vbase[ANSTG];
#pragma unroll
    for (int s = 0; s < ANSTG; s++) {
        kbase[s] = qbase + QBYTES + s * KVSTG;
        vbase[s] = kbase[s] + KVTILE;
    }

    const int tid  = threadIdx.x;
    const int wid  = tid >> 5;
    const int lane = tid & 31;
    const int grp  = lane >> 2;
    const int qid  = lane & 3;
    const int rw0  = wid * 16;

    const int qt = blockIdx.x;
    const int h  = blockIdx.y;
    const int b  = blockIdx.z;
    const int q0 = qt * QR;
    const size_t base = ((size_t)b * TSEQ) * CDIM + (size_t)h * HD;

    const int a_lrow = (lane & 7) + ((lane >> 3) & 1) * 8;
    const int a_lcol = (lane >> 4) * 8;
    const uint32_t q_off = (uint32_t)((rw0 + a_lrow) * QSTRH + a_lcol);
    const uint32_t k_off = (uint32_t)(((lane & 7) + (lane >> 4) * 8) * KVSTR +
                                      ((lane >> 3) & 1) * 8);
    const uint32_t v_off = (uint32_t)((lane & 15) * KVSTR + (lane >> 4) * 8);

    // Q -> smem
    __half* qsm = (__half*)dsm;
    for (int e = tid; e < QR * 32; e += 256) {
        int r = e >> 5, c2 = e & 31;
        *(half2*)&qsm[r * QSTRH + 2 * c2] =
            *(const half2*)&qg[base + (size_t)(q0 + r) * CDIM + 2 * c2];
    }

#define LOAD_KV(stg, kt_)                                                          \
    do {                                                                           \
        const int _k0 = (kt_) * 64;                                                \
        _Pragma("unroll")                                                          \
        for (int _q = 0; _q < 2; _q++) {                                           \
            int _e = _q * 256 + tid; int _r = _e >> 3, _c = _e & 7;                \
            cp_async16(kbase[(stg)] + (uint32_t)(_r * KVSTR + _c * 8) * 2,         \
                       &kg[base + (size_t)(_k0 + _r) * CDIM + _c * 8]);            \
        }                                                                          \
        _Pragma("unroll")                                                          \
        for (int _q = 0; _q < 2; _q++) {                                           \
            int _e = _q * 256 + tid; int _r = _e >> 3, _c = _e & 7;                \
            cp_async16(vbase[(stg)] + (uint32_t)(_r * KVSTR + _c * 8) * 2,         \
                       &vg[base + (size_t)(_k0 + _r) * CDIM + _c * 8]);            \
        }                                                                          \
    } while (0)

    const int kt_lo = (q0 >= WIN) ? ((q0 - WIN) >> 6) : 0;
    const int kt_hi = (q0 >> 6) + 1;
    const int nkt   = kt_hi - kt_lo + 1;

    LOAD_KV(0, kt_lo);
    cp_commit();
    if (nkt > 1) LOAD_KV(1, kt_lo + 1);
    cp_commit();

    // hoist loop-invariant Q fragments (needs a barrier after the Q stores)
    __syncthreads();
    uint32_t qf[4][4];
#pragma unroll
    for (int ks16 = 0; ks16 < 4; ks16++)
        ldmatrix_x4(qf[ks16][0], qf[ks16][1], qf[ks16][2], qf[ks16][3],
                    qbase + (q_off + ks16 * 16) * 2);

    float m_lo = -INFINITY, m_hi = -INFINITY;
    float l_lo = 0.f, l_hi = 0.f;
    float oacc[8][4];
#pragma unroll
    for (int j = 0; j < 8; j++)
#pragma unroll
        for (int r = 0; r < 4; r++) oacc[j][r] = 0.f;

    const int r0  = rw0 + grp;
    const int gi0 = q0 + r0, gi1 = gi0 + 8;

    for (int idx = 0; idx < nkt; idx++) {
        cp_wait<1>();
        __syncthreads();
        if (idx + 2 < nkt) LOAD_KV((idx + 2) % ANSTG, kt_lo + idx + 2);
        cp_commit();

        const int kt = kt_lo + idx;
        const int k0 = kt * 64;
        const int st = idx % ANSTG;

        const int i_lo = q0 + rw0, i_hi = i_lo + 15;
        if ((k0 > i_hi) || (i_lo - (k0 + 63) > WIN)) continue;
        const bool full_valid = (k0 + 63 <= i_lo) && (i_hi - k0 <= WIN);

        // ---- S = Q K^T (already scaled: log2-domain scores) ----
        float sacc[8][4];
#pragma unroll
        for (int j = 0; j < 8; j++)
#pragma unroll
            for (int r = 0; r < 4; r++) sacc[j][r] = 0.f;
#pragma unroll
        for (int ks16 = 0; ks16 < 4; ks16++) {
            const int kb = ks16 * 16;
#pragma unroll
            for (int jp = 0; jp < 4; jp++) {
                uint32_t b0, b1, b2, b3;
                ldmatrix_x4(b0, b1, b2, b3,
                            kbase[st] + (k_off + (uint32_t)(jp * 16 * KVSTR + kb)) * 2);
                uint32_t bj0[2] = { b0, b1 };
                uint32_t bj1[2] = { b2, b3 };
                mma_f16(sacc[jp * 2],     qf[ks16], bj0);
                mma_f16(sacc[jp * 2 + 1], qf[ks16], bj1);
            }
        }

        // ---- mask (no scaling needed) ----
        if (!full_valid) {
#pragma unroll
            for (int j = 0; j < 8; j++) {
                const int gj0 = k0 + j * 8 + 2 * qid, gj1 = gj0 + 1;
                const int d00 = gi0 - gj0, d01 = gi0 - gj1;
                const int d10 = gi1 - gj0, d11 = gi1 - gj1;
                if (!(d00 >= 0 && d00 <= WIN)) sacc[j][0] = -INFINITY;
                if (!(d01 >= 0 && d01 <= WIN)) sacc[j][1] = -INFINITY;
                if (!(d10 >= 0 && d10 <= WIN)) sacc[j][2] = -INFINITY;
                if (!(d11 >= 0 && d11 <= WIN)) sacc[j][3] = -INFINITY;
            }
        }

        // ---- online softmax in exp2 domain ----
        float ml = -INFINITY, mh = -INFINITY;
#pragma unroll
        for (int j = 0; j < 8; j++) {
            ml = fmaxf(ml, fmaxf(sacc[j][0], sacc[j][1]));
            mh = fmaxf(mh, fmaxf(sacc[j][2], sacc[j][3]));
        }
        ml = fmaxf(ml, __shfl_xor_sync(0xffffffffu, ml, 1));
        ml = fmaxf(ml, __shfl_xor_sync(0xffffffffu, ml, 2));
        mh = fmaxf(mh, __shfl_xor_sync(0xffffffffu, mh, 1));
        mh = fmaxf(mh, __shfl_xor_sync(0xffffffffu, mh, 2));

        const float mnl = fmaxf(m_lo, ml), mnh = fmaxf(m_hi, mh);
        const float msl = fmaxf(mnl, -1e30f), msh = fmaxf(mnh, -1e30f);
        const float al_lo = exp2f(m_lo - msl), al_hi = exp2f(m_hi - msh);

        uint32_t ph[8][2];
        float sl = 0.f, sh = 0.f;
#pragma unroll
        for (int j = 0; j < 8; j++) {
            float p0 = exp2f(sacc[j][0] - msl);
            float p1 = exp2f(sacc[j][1] - msl);
            float p2 = exp2f(sacc[j][2] - msh);
            float p3 = exp2f(sacc[j][3] - msh);
            sl += p0 + p1;
            sh += p2 + p3;
            ph[j][0] = packh2(p0, p1);
            ph[j][1] = packh2(p2, p3);
        }
        sl += __shfl_xor_sync(0xffffffffu, sl, 1);
        sl += __shfl_xor_sync(0xffffffffu, sl, 2);
        sh += __shfl_xor_sync(0xffffffffu, sh, 1);
        sh += __shfl_xor_sync(0xffffffffu, sh, 2);

        l_lo = l_lo * al_lo + sl;
        l_hi = l_hi * al_hi + sh;
        m_lo = mnl;
        m_hi = mnh;
#pragma unroll
        for (int j = 0; j < 8; j++) {
            oacc[j][0] *= al_lo; oacc[j][1] *= al_lo;
            oacc[j][2] *= al_hi; oacc[j][3] *= al_hi;
        }

        // ---- O += P @ V ----
#pragma unroll
        for (int ks16 = 0; ks16 < 4; ks16++) {
            const int kb = ks16 * 16;
            uint32_t af[4];
            af[0] = ph[2 * ks16][0];
            af[1] = ph[2 * ks16][1];
            af[2] = ph[2 * ks16 + 1][0];
            af[3] = ph[2 * ks16 + 1][1];
#pragma unroll
            for (int jp = 0; jp < 4; jp++) {
                uint32_t b0, b1, b2, b3;
                ldmatrix_x4t(b0, b1, b2, b3,
                             vbase[st] + (v_off + (uint32_t)(kb * KVSTR + jp * 16)) * 2);
                uint32_t bj0[2] = { b0, b1 };
                uint32_t bj1[2] = { b2, b3 };
                mma_f16(oacc[jp * 2],     af, bj0);
                mma_f16(oacc[jp * 2 + 1], af, bj1);
            }
        }
    }

    // epilogue
    {
        const float inv_lo = 1.0f / l_lo;
        const float inv_hi = 1.0f / l_hi;
#pragma unroll
        for (int j = 0; j < 8; j++) {
            const int col = j * 8 + 2 * qid;
            *(half2*)&yg[base + (size_t)(q0 + r0) * CDIM + col] =
                __floats2half2_rn(oacc[j][0] * inv_lo, oacc[j][1] * inv_lo);
            *(half2*)&yg[base + (size_t)(q0 + r0 + 8) * CDIM + col] =
                __floats2half2_rn(oacc[j][2] * inv_hi, oacc[j][3] * inv_hi);
        }
    }
#undef LOAD_KV
}

// ---------------------------------------------------------------------------
extern "C" void kernel_launch(void* const* d_in, const int* in_sizes, int n_in,
                              void* d_out, int out_size)
{
    const float* x  = (const float*)d_in[0];
    const float* Wq = (const float*)d_in[1];
    const float* bq = (const float*)d_in[2];
    const float* Wk = (const float*)d_in[3];
    const float* bk = (const float*)d_in[4];
    const float* Wv = (const float*)d_in[5];
    const float* bv = (const float*)d_in[6];
    const float* Wo = (const float*)d_in[7];
    const float* bo = (const float*)d_in[8];
    float* out = (float*)d_out;
    (void)in_sizes; (void)n_in; (void)out_size;

    __half *qp, *kp, *vp, *yp, *xhp, *whp;
    cudaGetSymbolAddress((void**)&qp,  g_q);
    cudaGetSymbolAddress((void**)&kp,  g_k);
    cudaGetSymbolAddress((void**)&vp,  g_v);
    cudaGetSymbolAddress((void**)&yp,  g_y);
    cudaGetSymbolAddress((void**)&xhp, g_xh);
    cudaGetSymbolAddress((void**)&whp, g_wh);
    __half* who = whp + 3 * (size_t)CDIM * CDIM;

    cudaFuncSetAttribute(attn_kernel,
                         cudaFuncAttributeMaxDynamicSharedMemorySize, ATT_SMEM_B);
    cudaFuncSetAttribute(gemm_qkv_kernel,
                         cudaFuncAttributeMaxDynamicSharedMemorySize, GEMM_SMEM);
    cudaFuncSetAttribute(gemm_out_kernel,
                         cudaFuncAttributeMaxDynamicSharedMemorySize, GEMM_SMEM);

    const int TOT4 = NX4 + 4 * NW4;
    cvt_all_kernel<<<(TOT4 + 255) / 256, 256>>>(x, Wq, Wk, Wv, Wo, xhp, whp);

    gemm_qkv_kernel<<<dim3(24, MROWS / BM), 256, GEMM_SMEM>>>(xhp, whp, bq, bk, bv,
                                                              qp, kp, vp);

    attn_kernel<<<dim3(TSEQ / QR, NHEAD, BATCH), 256, ATT_SMEM_B>>>(qp, kp, vp, yp);

    gemm_out_kernel<<<dim3(CDIM / BN, MROWS / BM), 256, GEMM_SMEM>>>(yp, who, bo, out);
}

// round 16
// speedup vs baseline: 1.0005x; 1.0005x over previous
#include <cuda_runtime.h>
#include <cuda_fp16.h>
#include <math.h>
#include <stdint.h>

#define TSEQ   2048
#define BATCH  2
#define CDIM   1024
#define NHEAD  16
#define HD     64
#define WIN    256
#define MROWS  (BATCH*TSEQ)   /* 4096 */

// Scratch (allocation-free rule: __device__ globals; uint16 = half storage)
static __device__ unsigned short g_q[(size_t)MROWS*CDIM];
static __device__ unsigned short g_k[(size_t)MROWS*CDIM];
static __device__ unsigned short g_v[(size_t)MROWS*CDIM];
static __device__ unsigned short g_y[(size_t)MROWS*CDIM];
static __device__ unsigned short g_xh[(size_t)MROWS*CDIM];
static __device__ unsigned short g_wh[4][(size_t)CDIM*CDIM];

// ===========================================================================
// PTX helpers
// ===========================================================================
__device__ __forceinline__ uint32_t smem_u32(const void* p) {
    uint32_t a;
    asm("{ .reg .u64 t; cvta.to.shared.u64 t, %1; cvt.u32.u64 %0, t; }" : "=r"(a) : "l"(p));
    return a;
}
__device__ __forceinline__ void cp_async16(uint32_t s, const void* g) {
    asm volatile("cp.async.cg.shared.global [%0], [%1], 16;" :: "r"(s), "l"(g) : "memory");
}
__device__ __forceinline__ void cp_commit() {
    asm volatile("cp.async.commit_group;" ::: "memory");
}
template <int N_>
__device__ __forceinline__ void cp_wait() {
    asm volatile("cp.async.wait_group %0;" :: "n"(N_) : "memory");
}
// PDL: allow dependents to be dispatched; wait for prior grid completion+flush.
__device__ __forceinline__ void gdc_launch() {
    asm volatile("griddepcontrol.launch_dependents;");
}
__device__ __forceinline__ void gdc_wait() {
    asm volatile("griddepcontrol.wait;" ::: "memory");
}
__device__ __forceinline__ void mma_f16(float* c, const uint32_t* a, const uint32_t* b) {
    asm volatile(
        "mma.sync.aligned.m16n8k16.row.col.f32.f16.f16.f32 "
        "{%0,%1,%2,%3}, {%4,%5,%6,%7}, {%8,%9}, {%0,%1,%2,%3};"
        : "+f"(c[0]), "+f"(c[1]), "+f"(c[2]), "+f"(c[3])
        : "r"(a[0]), "r"(a[1]), "r"(a[2]), "r"(a[3]), "r"(b[0]), "r"(b[1]));
}
__device__ __forceinline__ void ldmatrix_x4(uint32_t& r0, uint32_t& r1,
                                            uint32_t& r2, uint32_t& r3, uint32_t addr) {
    asm volatile("ldmatrix.sync.aligned.m8n8.x4.shared.b16 {%0,%1,%2,%3}, [%4];"
                 : "=r"(r0), "=r"(r1), "=r"(r2), "=r"(r3) : "r"(addr));
}
__device__ __forceinline__ void ldmatrix_x4t(uint32_t& r0, uint32_t& r1,
                                             uint32_t& r2, uint32_t& r3, uint32_t addr) {
    asm volatile("ldmatrix.sync.aligned.m8n8.x4.trans.shared.b16 {%0,%1,%2,%3}, [%4];"
                 : "=r"(r0), "=r"(r1), "=r"(r2), "=r"(r3) : "r"(addr));
}
__device__ __forceinline__ uint32_t packh2(float a, float b) {
    half2 h = __floats2half2_rn(a, b);
    return *(uint32_t*)&h;
}

// ===========================================================================
// Fused prepass: float -> half for X and all 4 weights, one launch.
// ===========================================================================
#define NX4 (MROWS * CDIM / 4)
#define NW4 (CDIM * CDIM / 4)

__global__ void cvt_all_kernel(const float* __restrict__ x,
                               const float* __restrict__ w0, const float* __restrict__ w1,
                               const float* __restrict__ w2, const float* __restrict__ w3,
                               __half* __restrict__ xh, __half* __restrict__ wh)
{
    gdc_launch();
    int i = blockIdx.x * blockDim.x + threadIdx.x;
    const float* src;
    __half* dst;
    int off;
    if (i < NX4) {
        src = x; dst = xh; off = i;
    } else {
        int j = i - NX4;
        int m = j / NW4;
        off = j - m * NW4;
        src = (m == 0) ? w0 : (m == 1) ? w1 : (m == 2) ? w2 : w3;
        dst = wh + (size_t)m * CDIM * CDIM;
    }
    float4 v = ((const float4*)src)[off];
    ((half2*)dst)[2 * off]     = __floats2half2_rn(v.x, v.y);
    ((half2*)dst)[2 * off + 1] = __floats2half2_rn(v.z, v.w);
}

// ===========================================================================
// fp16 mma GEMM core (R12 config — at the legacy-HMMA throughput floor).
// oscale multiplies the (x@W + b) output (folds softmax scale into Q).
// ===========================================================================
#define BM 128
#define BN 128
#define BKH 64
#define NSTG 3
#define ASTRH 72
#define BSTRH 136
#define ABYTES (BM * ASTRH * 2)
#define BBYTES (BKH * BSTRH * 2)
#define STAGEB (ABYTES + BBYTES)
#define GEMM_SMEM (NSTG * STAGEB)

__device__ __forceinline__ void gemm_core(const __half* __restrict__ X,
                                          const __half* __restrict__ W,
                                          const float* __restrict__ bias,
                                          float* __restrict__ Yf,
                                          __half* __restrict__ Yh,
                                          int m0, int n0, float oscale, char* dsm)
{
    const int tid  = threadIdx.x;
    const int wid  = tid >> 5;
    const int lane = tid & 31;
    const int wm   = wid & 1;
    const int wn   = wid >> 1;
    const int grp  = lane >> 2;
    const int qid  = lane & 3;

    const uint32_t sbase = smem_u32(dsm);
    uint32_t sAb[NSTG], sBb[NSTG];
#pragma unroll
    for (int s = 0; s < NSTG; s++) {
        sAb[s] = sbase + s * STAGEB;
        sBb[s] = sbase + s * STAGEB + ABYTES;
    }

    float c[4][4][4];
#pragma unroll
    for (int i = 0; i < 4; i++)
#pragma unroll
        for (int j = 0; j < 4; j++)
#pragma unroll
            for (int r = 0; r < 4; r++) c[i][j][r] = 0.f;

    const int a_lrow = (lane & 7) + ((lane >> 3) & 1) * 8;
    const int a_lcol = (lane >> 4) * 8;
    const int b_lcol = (lane >> 4) * 8;
    const int b_lrow = lane & 15;

#define LOAD_STAGE(stg, kk0)                                                       \
    do {                                                                           \
        _Pragma("unroll")                                                          \
        for (int _q = 0; _q < 4; _q++) {                                           \
            int _t = _q * 256 + tid; int _r = _t >> 3, _c = _t & 7;                \
            cp_async16(sAb[(stg)] + (uint32_t)(_r * ASTRH + _c * 8) * 2,           \
                       &X[(size_t)(m0 + _r) * CDIM + (kk0) + _c * 8]);             \
        }                                                                          \
        _Pragma("unroll")                                                          \
        for (int _q = 0; _q < 4; _q++) {                                           \
            int _t = _q * 256 + tid; int _r = _t >> 4, _c = _t & 15;               \
            cp_async16(sBb[(stg)] + (uint32_t)(_r * BSTRH + _c * 8) * 2,           \
                       &W[(size_t)((kk0) + _r) * CDIM + n0 + _c * 8]);             \
        }                                                                          \
    } while (0)

#pragma unroll
    for (int ps = 0; ps < NSTG - 1; ps++) {
        LOAD_STAGE(ps, ps * BKH);
        cp_commit();
    }

    const int NIT = CDIM / BKH;
    for (int kt = 0; kt < NIT; kt++) {
        cp_wait<NSTG - 2>();
        __syncthreads();

        if (kt + NSTG - 1 < NIT)
            LOAD_STAGE((kt + NSTG - 1) % NSTG, (kt + NSTG - 1) * BKH);
        cp_commit();

        const int st = kt % NSTG;
        const uint32_t sAa = sAb[st];
        const uint32_t sBa = sBb[st];
#pragma unroll
        for (int kk = 0; kk < 4; kk++) {
            const int kb = kk * 16;
            uint32_t af[4][4];
#pragma unroll
            for (int i = 0; i < 4; i++) {
                const int row = wm * 64 + i * 16 + a_lrow;
                ldmatrix_x4(af[i][0], af[i][1], af[i][2], af[i][3],
                            sAa + (uint32_t)(row * ASTRH + kb + a_lcol) * 2);
            }
#pragma unroll
            for (int jp = 0; jp < 2; jp++) {
                const int col  = wn * 32 + jp * 16 + b_lcol;
                const int krow = kb + b_lrow;
                uint32_t b0, b1, b2, b3;
                ldmatrix_x4t(b0, b1, b2, b3, sBa + (uint32_t)(krow * BSTRH + col) * 2);
                uint32_t bj0[2] = { b0, b1 };
                uint32_t bj1[2] = { b2, b3 };
#pragma unroll
                for (int i = 0; i < 4; i++) {
                    mma_f16(c[i][jp * 2],     af[i], bj0);
                    mma_f16(c[i][jp * 2 + 1], af[i], bj1);
                }
            }
        }
    }

#pragma unroll
    for (int i = 0; i < 4; i++) {
        const int row = m0 + wm * 64 + i * 16 + grp;
#pragma unroll
        for (int j = 0; j < 4; j++) {
            const int col = n0 + wn * 32 + j * 8 + 2 * qid;
            const float b0 = bias[col], b1 = bias[col + 1];
            const float o0 = (c[i][j][0] + b0) * oscale, o1 = (c[i][j][1] + b1) * oscale;
            const float o2 = (c[i][j][2] + b0) * oscale, o3 = (c[i][j][3] + b1) * oscale;
            if (Yh) {
                *(half2*)&Yh[(size_t)row * CDIM + col]       = __floats2half2_rn(o0, o1);
                *(half2*)&Yh[(size_t)(row + 8) * CDIM + col] = __floats2half2_rn(o2, o3);
            } else {
                float2 v0 = { o0, o1 }, v1 = { o2, o3 };
                *(float2*)&Yf[(size_t)row * CDIM + col]       = v0;
                *(float2*)&Yf[(size_t)(row + 8) * CDIM + col] = v1;
            }
        }
    }
#undef LOAD_STAGE
}

// 0.125 * log2(e): folds 1/sqrt(64) softmax scale + exp->exp2 into Q.
#define QSCALE 0.1803368801111204f

__global__ __launch_bounds__(256, 2)
void gemm_qkv_kernel(const __half* __restrict__ X, const __half* __restrict__ whBase,
                     const float* __restrict__ bq, const float* __restrict__ bk,
                     const float* __restrict__ bv,
                     __half* __restrict__ qo, __half* __restrict__ ko,
                     __half* __restrict__ vo)
{
    extern __shared__ __align__(16) char dsm_g[];
    gdc_launch();
    const int msel = blockIdx.x >> 3;
    const int n0   = (blockIdx.x & 7) * BN;
    const int m0   = blockIdx.y * BM;
    const __half* W = whBase + (size_t)msel * CDIM * CDIM;
    const float* bias = (msel == 0) ? bq : (msel == 1) ? bk : bv;
    __half* Yh = (msel == 0) ? qo : (msel == 1) ? ko : vo;
    const float os = (msel == 0) ? QSCALE : 1.0f;
    gdc_wait();   // X, W produced by cvt
    gemm_core(X, W, bias, nullptr, Yh, m0, n0, os, dsm_g);
}

__global__ __launch_bounds__(256, 2)
void gemm_out_kernel(const __half* __restrict__ X, const __half* __restrict__ W,
                     const float* __restrict__ bias, float* __restrict__ Yf)
{
    extern __shared__ __align__(16) char dsm_g[];
    gdc_launch();
    const int m0 = blockIdx.y * BM;
    const int n0 = blockIdx.x * BN;
    gdc_wait();   // X produced by attn (W by cvt, transitively ordered)
    gemm_core(X, W, bias, Yf, nullptr, m0, n0, 1.0f, dsm_g);
}

// ---------------------------------------------------------------------------
// FA2-style sliding-window attention. Q pre-scaled by 0.125*log2e ->
// softmax in exp2 domain. Q fragments hoisted into registers.
// ---------------------------------------------------------------------------
#define QR     128
#define QSTRH  72
#define KVSTR  72
#define QBYTES (QR * QSTRH * 2)
#define KVTILE (64 * KVSTR * 2)
#define KVSTG  (2 * KVTILE)
#define ANSTG  3
#define ATT_SMEM_B (QBYTES + ANSTG * KVSTG)

__global__ __launch_bounds__(256, 2)
void attn_kernel(const __half* __restrict__ qg, const __half* __restrict__ kg,
                 const __half* __restrict__ vg, __half* __restrict__ yg)
{
    extern __shared__ __align__(16) char dsm[];
    gdc_launch();
    const uint32_t qbase = smem_u32(dsm);
    uint32_t kbase[ANSTG], vbase[ANSTG];
#pragma unroll
    for (int s = 0; s < ANSTG; s++) {
        kbase[s] = qbase + QBYTES + s * KVSTG;
        vbase[s] = kbase[s] + KVTILE;
    }

    const int tid  = threadIdx.x;
    const int wid  = tid >> 5;
    const int lane = tid & 31;
    const int grp  = lane >> 2;
    const int qid  = lane & 3;
    const int rw0  = wid * 16;

    const int qt = blockIdx.x;
    const int h  = blockIdx.y;
    const int b  = blockIdx.z;
    const int q0 = qt * QR;
    const size_t base = ((size_t)b * TSEQ) * CDIM + (size_t)h * HD;

    const int a_lrow = (lane & 7) + ((lane >> 3) & 1) * 8;
    const int a_lcol = (lane >> 4) * 8;
    const uint32_t q_off = (uint32_t)((rw0 + a_lrow) * QSTRH + a_lcol);
    const uint32_t k_off = (uint32_t)(((lane & 7) + (lane >> 4) * 8) * KVSTR +
                                      ((lane >> 3) & 1) * 8);
    const uint32_t v_off = (uint32_t)((lane & 15) * KVSTR + (lane >> 4) * 8);

    gdc_wait();   // q/k/v produced by QKV gemm

    // Q -> smem
    __half* qsm = (__half*)dsm;
    for (int e = tid; e < QR * 32; e += 256) {
        int r = e >> 5, c2 = e & 31;
        *(half2*)&qsm[r * QSTRH + 2 * c2] =
            *(const half2*)&qg[base + (size_t)(q0 + r) * CDIM + 2 * c2];
    }

#define LOAD_KV(stg, kt_)                                                          \
    do {                                                                           \
        const int _k0 = (kt_) * 64;                                                \
        _Pragma("unroll")                                                          \
        for (int _q = 0; _q < 2; _q++) {                                           \
            int _e = _q * 256 + tid; int _r = _e >> 3, _c = _e & 7;                \
            cp_async16(kbase[(stg)] + (uint32_t)(_r * KVSTR + _c * 8) * 2,         \
                       &kg[base + (size_t)(_k0 + _r) * CDIM + _c * 8]);            \
        }                                                                          \
        _Pragma("unroll")                                                          \
        for (int _q = 0; _q < 2; _q++) {                                           \
            int _e = _q * 256 + tid; int _r = _e >> 3, _c = _e & 7;                \
            cp_async16(vbase[(stg)] + (uint32_t)(_r * KVSTR + _c * 8) * 2,         \
                       &vg[base + (size_t)(_k0 + _r) * CDIM + _c * 8]);            \
        }                                                                          \
    } while (0)

    const int kt_lo = (q0 >= WIN) ? ((q0 - WIN) >> 6) : 0;
    const int kt_hi = (q0 >> 6) + 1;
    const int nkt   = kt_hi - kt_lo + 1;

    LOAD_KV(0, kt_lo);
    cp_commit();
    if (nkt > 1) LOAD_KV(1, kt_lo + 1);
    cp_commit();

    // hoist loop-invariant Q fragments
    __syncthreads();
    uint32_t qf[4][4];
#pragma unroll
    for (int ks16 = 0; ks16 < 4; ks16++)
        ldmatrix_x4(qf[ks16][0], qf[ks16][1], qf[ks16][2], qf[ks16][3],
                    qbase + (q_off + ks16 * 16) * 2);

    float m_lo = -INFINITY, m_hi = -INFINITY;
    float l_lo = 0.f, l_hi = 0.f;
    float oacc[8][4];
#pragma unroll
    for (int j = 0; j < 8; j++)
#pragma unroll
        for (int r = 0; r < 4; r++) oacc[j][r] = 0.f;

    const int r0  = rw0 + grp;
    const int gi0 = q0 + r0, gi1 = gi0 + 8;

    for (int idx = 0; idx < nkt; idx++) {
        cp_wait<1>();
        __syncthreads();
        if (idx + 2 < nkt) LOAD_KV((idx + 2) % ANSTG, kt_lo + idx + 2);
        cp_commit();

        const int kt = kt_lo + idx;
        const int k0 = kt * 64;
        const int st = idx % ANSTG;

        const int i_lo = q0 + rw0, i_hi = i_lo + 15;
        if ((k0 > i_hi) || (i_lo - (k0 + 63) > WIN)) continue;
        const bool full_valid = (k0 + 63 <= i_lo) && (i_hi - k0 <= WIN);

        // ---- S = Q K^T ----
        float sacc[8][4];
#pragma unroll
        for (int j = 0; j < 8; j++)
#pragma unroll
            for (int r = 0; r < 4; r++) sacc[j][r] = 0.f;
#pragma unroll
        for (int ks16 = 0; ks16 < 4; ks16++) {
            const int kb = ks16 * 16;
#pragma unroll
            for (int jp = 0; jp < 4; jp++) {
                uint32_t b0, b1, b2, b3;
                ldmatrix_x4(b0, b1, b2, b3,
                            kbase[st] + (k_off + (uint32_t)(jp * 16 * KVSTR + kb)) * 2);
                uint32_t bj0[2] = { b0, b1 };
                uint32_t bj1[2] = { b2, b3 };
                mma_f16(sacc[jp * 2],     qf[ks16], bj0);
                mma_f16(sacc[jp * 2 + 1], qf[ks16], bj1);
            }
        }

        // ---- mask ----
        if (!full_valid) {
#pragma unroll
            for (int j = 0; j < 8; j++) {
                const int gj0 = k0 + j * 8 + 2 * qid, gj1 = gj0 + 1;
                const int d00 = gi0 - gj0, d01 = gi0 - gj1;
                const int d10 = gi1 - gj0, d11 = gi1 - gj1;
                if (!(d00 >= 0 && d00 <= WIN)) sacc[j][0] = -INFINITY;
                if (!(d01 >= 0 && d01 <= WIN)) sacc[j][1] = -INFINITY;
                if (!(d10 >= 0 && d10 <= WIN)) sacc[j][2] = -INFINITY;
                if (!(d11 >= 0 && d11 <= WIN)) sacc[j][3] = -INFINITY;
            }
        }

        // ---- online softmax (exp2 domain) ----
        float ml = -INFINITY, mh = -INFINITY;
#pragma unroll
        for (int j = 0; j < 8; j++) {
            ml = fmaxf(ml, fmaxf(sacc[j][0], sacc[j][1]));
            mh = fmaxf(mh, fmaxf(sacc[j][2], sacc[j][3]));
        }
        ml = fmaxf(ml, __shfl_xor_sync(0xffffffffu, ml, 1));
        ml = fmaxf(ml, __shfl_xor_sync(0xffffffffu, ml, 2));
        mh = fmaxf(mh, __shfl_xor_sync(0xffffffffu, mh, 1));
        mh = fmaxf(mh, __shfl_xor_sync(0xffffffffu, mh, 2));

        const float mnl = fmaxf(m_lo, ml), mnh = fmaxf(m_hi, mh);
        const float msl = fmaxf(mnl, -1e30f), msh = fmaxf(mnh, -1e30f);
        const float al_lo = exp2f(m_lo - msl), al_hi = exp2f(m_hi - msh);

        uint32_t ph[8][2];
        float sl = 0.f, sh = 0.f;
#pragma unroll
        for (int j = 0; j < 8; j++) {
            float p0 = exp2f(sacc[j][0] - msl);
            float p1 = exp2f(sacc[j][1] - msl);
            float p2 = exp2f(sacc[j][2] - msh);
            float p3 = exp2f(sacc[j][3] - msh);
            sl += p0 + p1;
            sh += p2 + p3;
            ph[j][0] = packh2(p0, p1);
            ph[j][1] = packh2(p2, p3);
        }
        sl += __shfl_xor_sync(0xffffffffu, sl, 1);
        sl += __shfl_xor_sync(0xffffffffu, sl, 2);
        sh += __shfl_xor_sync(0xffffffffu, sh, 1);
        sh += __shfl_xor_sync(0xffffffffu, sh, 2);

        l_lo = l_lo * al_lo + sl;
        l_hi = l_hi * al_hi + sh;
        m_lo = mnl;
        m_hi = mnh;
#pragma unroll
        for (int j = 0; j < 8; j++) {
            oacc[j][0] *= al_lo; oacc[j][1] *= al_lo;
            oacc[j][2] *= al_hi; oacc[j][3] *= al_hi;
        }

        // ---- O += P @ V ----
#pragma unroll
        for (int ks16 = 0; ks16 < 4; ks16++) {
            const int kb = ks16 * 16;
            uint32_t af[4];
            af[0] = ph[2 * ks16][0];
            af[1] = ph[2 * ks16][1];
            af[2] = ph[2 * ks16 + 1][0];
            af[3] = ph[2 * ks16 + 1][1];
#pragma unroll
            for (int jp = 0; jp < 4; jp++) {
                uint32_t b0, b1, b2, b3;
                ldmatrix_x4t(b0, b1, b2, b3,
                             vbase[st] + (v_off + (uint32_t)(kb * KVSTR + jp * 16)) * 2);
                uint32_t bj0[2] = { b0, b1 };
                uint32_t bj1[2] = { b2, b3 };
                mma_f16(oacc[jp * 2],     af, bj0);
                mma_f16(oacc[jp * 2 + 1], af, bj1);
            }
        }
    }

    // epilogue
    {
        const float inv_lo = 1.0f / l_lo;
        const float inv_hi = 1.0f / l_hi;
#pragma unroll
        for (int j = 0; j < 8; j++) {
            const int col = j * 8 + 2 * qid;
            *(half2*)&yg[base + (size_t)(q0 + r0) * CDIM + col] =
                __floats2half2_rn(oacc[j][0] * inv_lo, oacc[j][1] * inv_lo);
            *(half2*)&yg[base + (size_t)(q0 + r0 + 8) * CDIM + col] =
                __floats2half2_rn(oacc[j][2] * inv_hi, oacc[j][3] * inv_hi);
        }
    }
#undef LOAD_KV
}

// ---------------------------------------------------------------------------
// Launch with PDL (programmatic stream serialization) on dependent kernels.
// ---------------------------------------------------------------------------
template <typename K, typename... Args>
static void launch_pdl(K kernel, dim3 grid, dim3 block, size_t smem, Args... args)
{
    cudaLaunchConfig_t cfg = {};
    cfg.gridDim = grid;
    cfg.blockDim = block;
    cfg.dynamicSmemBytes = smem;
    cudaLaunchAttribute attr[1];
    attr[0].id = cudaLaunchAttributeProgrammaticStreamSerialization;
    attr[0].val.programmaticStreamSerializationAllowed = 1;
    cfg.attrs = attr;
    cfg.numAttrs = 1;
    cudaLaunchKernelEx(&cfg, kernel, args...);
}

extern "C" void kernel_launch(void* const* d_in, const int* in_sizes, int n_in,
                              void* d_out, int out_size)
{
    const float* x  = (const float*)d_in[0];
    const float* Wq = (const float*)d_in[1];
    const float* bq = (const float*)d_in[2];
    const float* Wk = (const float*)d_in[3];
    const float* bk = (const float*)d_in[4];
    const float* Wv = (const float*)d_in[5];
    const float* bv = (const float*)d_in[6];
    const float* Wo = (const float*)d_in[7];
    const float* bo = (const float*)d_in[8];
    float* out = (float*)d_out;
    (void)in_sizes; (void)n_in; (void)out_size;

    __half *qp, *kp, *vp, *yp, *xhp, *whp;
    cudaGetSymbolAddress((void**)&qp,  g_q);
    cudaGetSymbolAddress((void**)&kp,  g_k);
    cudaGetSymbolAddress((void**)&vp,  g_v);
    cudaGetSymbolAddress((void**)&yp,  g_y);
    cudaGetSymbolAddress((void**)&xhp, g_xh);
    cudaGetSymbolAddress((void**)&whp, g_wh);
    __half* who = whp + 3 * (size_t)CDIM * CDIM;

    cudaFuncSetAttribute(attn_kernel,
                         cudaFuncAttributeMaxDynamicSharedMemorySize, ATT_SMEM_B);
    cudaFuncSetAttribute(gemm_qkv_kernel,
                         cudaFuncAttributeMaxDynamicSharedMemorySize, GEMM_SMEM);
    cudaFuncSetAttribute(gemm_out_kernel,
                         cudaFuncAttributeMaxDynamicSharedMemorySize, GEMM_SMEM);

    const int TOT4 = NX4 + 4 * NW4;
    cvt_all_kernel<<<(TOT4 + 255) / 256, 256>>>(x, Wq, Wk, Wv, Wo, xhp, whp);

    launch_pdl(gemm_qkv_kernel, dim3(24, MROWS / BM), dim3(256), (size_t)GEMM_SMEM,
               (const __half*)xhp, (const __half*)whp, bq, bk, bv, qp, kp, vp);

    launch_pdl(attn_kernel, dim3(TSEQ / QR, NHEAD, BATCH), dim3(256), (size_t)ATT_SMEM_B,
               (const __half*)qp, (const __half*)kp, (const __half*)vp, yp);

    launch_pdl(gemm_out_kernel, dim3(CDIM / BN, MROWS / BM), dim3(256), (size_t)GEMM_SMEM,
               (const __half*)yp, (const __half*)who, bo, out);
}

// round 17
// speedup vs baseline: 1.0082x; 1.0077x over previous
#include <cuda_runtime.h>
#include <cuda_fp16.h>
#include <math.h>
#include <stdint.h>

#define TSEQ   2048
#define BATCH  2
#define CDIM   1024
#define NHEAD  16
#define HD     64
#define WIN    256
#define MROWS  (BATCH*TSEQ)   /* 4096 */

// Scratch (allocation-free rule: __device__ globals; uint16 = half storage)
static __device__ unsigned short g_q[(size_t)MROWS*CDIM];
static __device__ unsigned short g_k[(size_t)MROWS*CDIM];
static __device__ unsigned short g_v[(size_t)MROWS*CDIM];
static __device__ unsigned short g_y[(size_t)MROWS*CDIM];
static __device__ unsigned short g_xh[(size_t)MROWS*CDIM];
static __device__ unsigned short g_wh[4][(size_t)CDIM*CDIM];

// ===========================================================================
// PTX helpers
// ===========================================================================
__device__ __forceinline__ uint32_t smem_u32(const void* p) {
    uint32_t a;
    asm("{ .reg .u64 t; cvta.to.shared.u64 t, %1; cvt.u32.u64 %0, t; }" : "=r"(a) : "l"(p));
    return a;
}
__device__ __forceinline__ void cp_async16(uint32_t s, const void* g) {
    asm volatile("cp.async.cg.shared.global [%0], [%1], 16;" :: "r"(s), "l"(g) : "memory");
}
__device__ __forceinline__ void cp_commit() {
    asm volatile("cp.async.commit_group;" ::: "memory");
}
template <int N_>
__device__ __forceinline__ void cp_wait() {
    asm volatile("cp.async.wait_group %0;" :: "n"(N_) : "memory");
}
__device__ __forceinline__ void gdc_launch() {
    asm volatile("griddepcontrol.launch_dependents;");
}
__device__ __forceinline__ void gdc_wait() {
    asm volatile("griddepcontrol.wait;" ::: "memory");
}
__device__ __forceinline__ void mma_f16(float* c, const uint32_t* a, const uint32_t* b) {
    asm volatile(
        "mma.sync.aligned.m16n8k16.row.col.f32.f16.f16.f32 "
        "{%0,%1,%2,%3}, {%4,%5,%6,%7}, {%8,%9}, {%0,%1,%2,%3};"
        : "+f"(c[0]), "+f"(c[1]), "+f"(c[2]), "+f"(c[3])
        : "r"(a[0]), "r"(a[1]), "r"(a[2]), "r"(a[3]), "r"(b[0]), "r"(b[1]));
}
__device__ __forceinline__ void ldmatrix_x4(uint32_t& r0, uint32_t& r1,
                                            uint32_t& r2, uint32_t& r3, uint32_t addr) {
    asm volatile("ldmatrix.sync.aligned.m8n8.x4.shared.b16 {%0,%1,%2,%3}, [%4];"
                 : "=r"(r0), "=r"(r1), "=r"(r2), "=r"(r3) : "r"(addr));
}
__device__ __forceinline__ void ldmatrix_x4t(uint32_t& r0, uint32_t& r1,
                                             uint32_t& r2, uint32_t& r3, uint32_t addr) {
    asm volatile("ldmatrix.sync.aligned.m8n8.x4.trans.shared.b16 {%0,%1,%2,%3}, [%4];"
                 : "=r"(r0), "=r"(r1), "=r"(r2), "=r"(r3) : "r"(addr));
}
__device__ __forceinline__ uint32_t packh2(float a, float b) {
    half2 h = __floats2half2_rn(a, b);
    return *(uint32_t*)&h;
}

// ===========================================================================
// Fused prepass: float -> half for X and all 4 weights, one launch.
// ===========================================================================
#define NX4 (MROWS * CDIM / 4)
#define NW4 (CDIM * CDIM / 4)

__global__ void cvt_all_kernel(const float* __restrict__ x,
                               const float* __restrict__ w0, const float* __restrict__ w1,
                               const float* __restrict__ w2, const float* __restrict__ w3,
                               __half* __restrict__ xh, __half* __restrict__ wh)
{
    gdc_launch();
    int i = blockIdx.x * blockDim.x + threadIdx.x;
    const float* src;
    __half* dst;
    int off;
    if (i < NX4) {
        src = x; dst = xh; off = i;
    } else {
        int j = i - NX4;
        int m = j / NW4;
        off = j - m * NW4;
        src = (m == 0) ? w0 : (m == 1) ? w1 : (m == 2) ? w2 : w3;
        dst = wh + (size_t)m * CDIM * CDIM;
    }
    float4 v = ((const float4*)src)[off];
    ((half2*)dst)[2 * off]     = __floats2half2_rn(v.x, v.y);
    ((half2*)dst)[2 * off + 1] = __floats2half2_rn(v.z, v.w);
}

// ===========================================================================
// fp16 mma GEMM core (R12 config — at the legacy-HMMA throughput floor).
// ===========================================================================
#define BM 128
#define BN 128
#define BKH 64
#define NSTG 3
#define ASTRH 72
#define BSTRH 136
#define ABYTES (BM * ASTRH * 2)
#define BBYTES (BKH * BSTRH * 2)
#define STAGEB (ABYTES + BBYTES)
#define GEMM_SMEM (NSTG * STAGEB)

__device__ __forceinline__ void gemm_core(const __half* __restrict__ X,
                                          const __half* __restrict__ W,
                                          const float* __restrict__ bias,
                                          float* __restrict__ Yf,
                                          __half* __restrict__ Yh,
                                          int m0, int n0, char* dsm)
{
    const int tid  = threadIdx.x;
    const int wid  = tid >> 5;
    const int lane = tid & 31;
    const int wm   = wid & 1;
    const int wn   = wid >> 1;
    const int grp  = lane >> 2;
    const int qid  = lane & 3;

    const uint32_t sbase = smem_u32(dsm);
    uint32_t sAb[NSTG], sBb[NSTG];
#pragma unroll
    for (int s = 0; s < NSTG; s++) {
        sAb[s] = sbase + s * STAGEB;
        sBb[s] = sbase + s * STAGEB + ABYTES;
    }

    float c[4][4][4];
#pragma unroll
    for (int i = 0; i < 4; i++)
#pragma unroll
        for (int j = 0; j < 4; j++)
#pragma unroll
            for (int r = 0; r < 4; r++) c[i][j][r] = 0.f;

    const int a_lrow = (lane & 7) + ((lane >> 3) & 1) * 8;
    const int a_lcol = (lane >> 4) * 8;
    const int b_lcol = (lane >> 4) * 8;
    const int b_lrow = lane & 15;

#define LOAD_STAGE(stg, kk0)                                                       \
    do {                                                                           \
        _Pragma("unroll")                                                          \
        for (int _q = 0; _q < 4; _q++) {                                           \
            int _t = _q * 256 + tid; int _r = _t >> 3, _c = _t & 7;                \
            cp_async16(sAb[(stg)] + (uint32_t)(_r * ASTRH + _c * 8) * 2,           \
                       &X[(size_t)(m0 + _r) * CDIM + (kk0) + _c * 8]);             \
        }                                                                          \
        _Pragma("unroll")                                                          \
        for (int _q = 0; _q < 4; _q++) {                                           \
            int _t = _q * 256 + tid; int _r = _t >> 4, _c = _t & 15;               \
            cp_async16(sBb[(stg)] + (uint32_t)(_r * BSTRH + _c * 8) * 2,           \
                       &W[(size_t)((kk0) + _r) * CDIM + n0 + _c * 8]);             \
        }                                                                          \
    } while (0)

#pragma unroll
    for (int ps = 0; ps < NSTG - 1; ps++) {
        LOAD_STAGE(ps, ps * BKH);
        cp_commit();
    }

    const int NIT = CDIM / BKH;
    for (int kt = 0; kt < NIT; kt++) {
        cp_wait<NSTG - 2>();
        __syncthreads();

        if (kt + NSTG - 1 < NIT)
            LOAD_STAGE((kt + NSTG - 1) % NSTG, (kt + NSTG - 1) * BKH);
        cp_commit();

        const int st = kt % NSTG;
        const uint32_t sAa = sAb[st];
        const uint32_t sBa = sBb[st];
#pragma unroll
        for (int kk = 0; kk < 4; kk++) {
            const int kb = kk * 16;
            uint32_t af[4][4];
#pragma unroll
            for (int i = 0; i < 4; i++) {
                const int row = wm * 64 + i * 16 + a_lrow;
                ldmatrix_x4(af[i][0], af[i][1], af[i][2], af[i][3],
                            sAa + (uint32_t)(row * ASTRH + kb + a_lcol) * 2);
            }
#pragma unroll
            for (int jp = 0; jp < 2; jp++) {
                const int col  = wn * 32 + jp * 16 + b_lcol;
                const int krow = kb + b_lrow;
                uint32_t b0, b1, b2, b3;
                ldmatrix_x4t(b0, b1, b2, b3, sBa + (uint32_t)(krow * BSTRH + col) * 2);
                uint32_t bj0[2] = { b0, b1 };
                uint32_t bj1[2] = { b2, b3 };
#pragma unroll
                for (int i = 0; i < 4; i++) {
                    mma_f16(c[i][jp * 2],     af[i], bj0);
                    mma_f16(c[i][jp * 2 + 1], af[i], bj1);
                }
            }
        }
    }

#pragma unroll
    for (int i = 0; i < 4; i++) {
        const int row = m0 + wm * 64 + i * 16 + grp;
#pragma unroll
        for (int j = 0; j < 4; j++) {
            const int col = n0 + wn * 32 + j * 8 + 2 * qid;
            const float b0 = bias[col], b1 = bias[col + 1];
            const float o0 = c[i][j][0] + b0, o1 = c[i][j][1] + b1;
            const float o2 = c[i][j][2] + b0, o3 = c[i][j][3] + b1;
            if (Yh) {
                *(half2*)&Yh[(size_t)row * CDIM + col]       = __floats2half2_rn(o0, o1);
                *(half2*)&Yh[(size_t)(row + 8) * CDIM + col] = __floats2half2_rn(o2, o3);
            } else {
                float2 v0 = { o0, o1 }, v1 = { o2, o3 };
                *(float2*)&Yf[(size_t)row * CDIM + col]       = v0;
                *(float2*)&Yf[(size_t)(row + 8) * CDIM + col] = v1;
            }
        }
    }
#undef LOAD_STAGE
}

__global__ __launch_bounds__(256, 2)
void gemm_qkv_kernel(const __half* __restrict__ X, const __half* __restrict__ whBase,
                     const float* __restrict__ bq, const float* __restrict__ bk,
                     const float* __restrict__ bv,
                     __half* __restrict__ qo, __half* __restrict__ ko,
                     __half* __restrict__ vo)
{
    extern __shared__ __align__(16) char dsm_g[];
    gdc_launch();
    const int msel = blockIdx.x >> 3;
    const int n0   = (blockIdx.x & 7) * BN;
    const int m0   = blockIdx.y * BM;
    const __half* W = whBase + (size_t)msel * CDIM * CDIM;
    const float* bias = (msel == 0) ? bq : (msel == 1) ? bk : bv;
    __half* Yh = (msel == 0) ? qo : (msel == 1) ? ko : vo;
    gdc_wait();
    gemm_core(X, W, bias, nullptr, Yh, m0, n0, dsm_g);
}

__global__ __launch_bounds__(256, 2)
void gemm_out_kernel(const __half* __restrict__ X, const __half* __restrict__ W,
                     const float* __restrict__ bias, float* __restrict__ Yf)
{
    extern __shared__ __align__(16) char dsm_g[];
    gdc_launch();
    const int m0 = blockIdx.y * BM;
    const int n0 = blockIdx.x * BN;
    gdc_wait();
    gemm_core(X, W, bias, Yf, nullptr, m0, n0, dsm_g);
}

// ---------------------------------------------------------------------------
// FA2-style sliding-window attention (exact R14 body + PDL hooks):
// Q-tile 128 x K-tile 64, register-resident softmax, 3-stage cp.async K/V,
// 1 barrier per k-tile.
// ---------------------------------------------------------------------------
#define QR     128
#define QSTRH  72
#define KVSTR  72
#define QBYTES (QR * QSTRH * 2)
#define KVTILE (64 * KVSTR * 2)
#define KVSTG  (2 * KVTILE)
#define ANSTG  3
#define ATT_SMEM_B (QBYTES + ANSTG * KVSTG)

__global__ __launch_bounds__(256)
void attn_kernel(const __half* __restrict__ qg, const __half* __restrict__ kg,
                 const __half* __restrict__ vg, __half* __restrict__ yg)
{
    extern __shared__ __align__(16) char dsm[];
    gdc_launch();
    const uint32_t qbase = smem_u32(dsm);
    uint32_t kbase[ANSTG], vbase[ANSTG];
#pragma unroll
    for (int s = 0; s < ANSTG; s++) {
        kbase[s] = qbase + QBYTES + s * KVSTG;
        vbase[s] = kbase[s] + KVTILE;
    }

    const int tid  = threadIdx.x;
    const int wid  = tid >> 5;
    const int lane = tid & 31;
    const int grp  = lane >> 2;
    const int qid  = lane & 3;
    const int rw0  = wid * 16;

    const int qt = blockIdx.x;
    const int h  = blockIdx.y;
    const int b  = blockIdx.z;
    const int q0 = qt * QR;
    const size_t base = ((size_t)b * TSEQ) * CDIM + (size_t)h * HD;

    const int a_lrow = (lane & 7) + ((lane >> 3) & 1) * 8;
    const int a_lcol = (lane >> 4) * 8;
    const uint32_t q_off = (uint32_t)((rw0 + a_lrow) * QSTRH + a_lcol);
    const uint32_t k_off = (uint32_t)(((lane & 7) + (lane >> 4) * 8) * KVSTR +
                                      ((lane >> 3) & 1) * 8);
    const uint32_t v_off = (uint32_t)((lane & 15) * KVSTR + (lane >> 4) * 8);

    gdc_wait();   // q/k/v produced by QKV gemm

    // Q -> smem
    __half* qsm = (__half*)dsm;
    for (int e = tid; e < QR * 32; e += 256) {
        int r = e >> 5, c2 = e & 31;
        *(half2*)&qsm[r * QSTRH + 2 * c2] =
            *(const half2*)&qg[base + (size_t)(q0 + r) * CDIM + 2 * c2];
    }

#define LOAD_KV(stg, kt_)                                                          \
    do {                                                                           \
        const int _k0 = (kt_) * 64;                                                \
        _Pragma("unroll")                                                          \
        for (int _q = 0; _q < 2; _q++) {                                           \
            int _e = _q * 256 + tid; int _r = _e >> 3, _c = _e & 7;                \
            cp_async16(kbase[(stg)] + (uint32_t)(_r * KVSTR + _c * 8) * 2,         \
                       &kg[base + (size_t)(_k0 + _r) * CDIM + _c * 8]);            \
        }                                                                          \
        _Pragma("unroll")                                                          \
        for (int _q = 0; _q < 2; _q++) {                                           \
            int _e = _q * 256 + tid; int _r = _e >> 3, _c = _e & 7;                \
            cp_async16(vbase[(stg)] + (uint32_t)(_r * KVSTR + _c * 8) * 2,         \
                       &vg[base + (size_t)(_k0 + _r) * CDIM + _c * 8]);            \
        }                                                                          \
    } while (0)

    const int kt_lo = (q0 >= WIN) ? ((q0 - WIN) >> 6) : 0;
    const int kt_hi = (q0 >> 6) + 1;
    const int nkt   = kt_hi - kt_lo + 1;

    LOAD_KV(0, kt_lo);
    cp_commit();
    if (nkt > 1) LOAD_KV(1, kt_lo + 1);
    cp_commit();

    float m_lo = -INFINITY, m_hi = -INFINITY;
    float l_lo = 0.f, l_hi = 0.f;
    float oacc[8][4];
#pragma unroll
    for (int j = 0; j < 8; j++)
#pragma unroll
        for (int r = 0; r < 4; r++) oacc[j][r] = 0.f;

    const int r0  = rw0 + grp;
    const int gi0 = q0 + r0, gi1 = gi0 + 8;

    for (int idx = 0; idx < nkt; idx++) {
        cp_wait<1>();
        __syncthreads();
        if (idx + 2 < nkt) LOAD_KV((idx + 2) % ANSTG, kt_lo + idx + 2);
        cp_commit();

        const int kt = kt_lo + idx;
        const int k0 = kt * 64;
        const int st = idx % ANSTG;

        const int i_lo = q0 + rw0, i_hi = i_lo + 15;
        if ((k0 > i_hi) || (i_lo - (k0 + 63) > WIN)) continue;
        const bool full_valid = (k0 + 63 <= i_lo) && (i_hi - k0 <= WIN);

        // ---- S = Q K^T (registers) ----
        float sacc[8][4];
#pragma unroll
        for (int j = 0; j < 8; j++)
#pragma unroll
            for (int r = 0; r < 4; r++) sacc[j][r] = 0.f;
#pragma unroll
        for (int ks16 = 0; ks16 < 4; ks16++) {
            const int kb = ks16 * 16;
            uint32_t af[4];
            ldmatrix_x4(af[0], af[1], af[2], af[3], qbase + (q_off + kb) * 2);
#pragma unroll
            for (int jp = 0; jp < 4; jp++) {
                uint32_t b0, b1, b2, b3;
                ldmatrix_x4(b0, b1, b2, b3,
                            kbase[st] + (k_off + (uint32_t)(jp * 16 * KVSTR + kb)) * 2);
                uint32_t bj0[2] = { b0, b1 };
                uint32_t bj1[2] = { b2, b3 };
                mma_f16(sacc[jp * 2],     af, bj0);
                mma_f16(sacc[jp * 2 + 1], af, bj1);
            }
        }

        // ---- scale + mask in registers ----
        if (full_valid) {
#pragma unroll
            for (int j = 0; j < 8; j++)
#pragma unroll
                for (int r = 0; r < 4; r++) sacc[j][r] *= 0.125f;
        } else {
#pragma unroll
            for (int j = 0; j < 8; j++) {
                const int gj0 = k0 + j * 8 + 2 * qid, gj1 = gj0 + 1;
                const int d00 = gi0 - gj0, d01 = gi0 - gj1;
                const int d10 = gi1 - gj0, d11 = gi1 - gj1;
                sacc[j][0] = (d00 >= 0 && d00 <= WIN) ? sacc[j][0] * 0.125f : -INFINITY;
                sacc[j][1] = (d01 >= 0 && d01 <= WIN) ? sacc[j][1] * 0.125f : -INFINITY;
                sacc[j][2] = (d10 >= 0 && d10 <= WIN) ? sacc[j][2] * 0.125f : -INFINITY;
                sacc[j][3] = (d11 >= 0 && d11 <= WIN) ? sacc[j][3] * 0.125f : -INFINITY;
            }
        }

        // ---- online softmax (registers; quad shfl) ----
        float ml = -INFINITY, mh = -INFINITY;
#pragma unroll
        for (int j = 0; j < 8; j++) {
            ml = fmaxf(ml, fmaxf(sacc[j][0], sacc[j][1]));
            mh = fmaxf(mh, fmaxf(sacc[j][2], sacc[j][3]));
        }
        ml = fmaxf(ml, __shfl_xor_sync(0xffffffffu, ml, 1));
        ml = fmaxf(ml, __shfl_xor_sync(0xffffffffu, ml, 2));
        mh = fmaxf(mh, __shfl_xor_sync(0xffffffffu, mh, 1));
        mh = fmaxf(mh, __shfl_xor_sync(0xffffffffu, mh, 2));

        const float mnl = fmaxf(m_lo, ml), mnh = fmaxf(m_hi, mh);
        const float msl = fmaxf(mnl, -1e30f), msh = fmaxf(mnh, -1e30f);
        const float al_lo = __expf(m_lo - msl), al_hi = __expf(m_hi - msh);

        uint32_t ph[8][2];
        float sl = 0.f, sh = 0.f;
#pragma unroll
        for (int j = 0; j < 8; j++) {
            float p0 = __expf(sacc[j][0] - msl);
            float p1 = __expf(sacc[j][1] - msl);
            float p2 = __expf(sacc[j][2] - msh);
            float p3 = __expf(sacc[j][3] - msh);
            sl += p0 + p1;
            sh += p2 + p3;
            ph[j][0] = packh2(p0, p1);
            ph[j][1] = packh2(p2, p3);
        }
        sl += __shfl_xor_sync(0xffffffffu, sl, 1);
        sl += __shfl_xor_sync(0xffffffffu, sl, 2);
        sh += __shfl_xor_sync(0xffffffffu, sh, 1);
        sh += __shfl_xor_sync(0xffffffffu, sh, 2);

        l_lo = l_lo * al_lo + sl;
        l_hi = l_hi * al_hi + sh;
        m_lo = mnl;
        m_hi = mnh;
#pragma unroll
        for (int j = 0; j < 8; j++) {
            oacc[j][0] *= al_lo; oacc[j][1] *= al_lo;
            oacc[j][2] *= al_hi; oacc[j][3] *= al_hi;
        }

        // ---- O += P @ V ----
#pragma unroll
        for (int ks16 = 0; ks16 < 4; ks16++) {
            const int kb = ks16 * 16;
            uint32_t af[4];
            af[0] = ph[2 * ks16][0];
            af[1] = ph[2 * ks16][1];
            af[2] = ph[2 * ks16 + 1][0];
            af[3] = ph[2 * ks16 + 1][1];
#pragma unroll
            for (int jp = 0; jp < 4; jp++) {
                uint32_t b0, b1, b2, b3;
                ldmatrix_x4t(b0, b1, b2, b3,
                             vbase[st] + (v_off + (uint32_t)(kb * KVSTR + jp * 16)) * 2);
                uint32_t bj0[2] = { b0, b1 };
                uint32_t bj1[2] = { b2, b3 };
                mma_f16(oacc[jp * 2],     af, bj0);
                mma_f16(oacc[jp * 2 + 1], af, bj1);
            }
        }
    }

    // epilogue
    {
        const float inv_lo = 1.0f / l_lo;
        const float inv_hi = 1.0f / l_hi;
#pragma unroll
        for (int j = 0; j < 8; j++) {
            const int col = j * 8 + 2 * qid;
            *(half2*)&yg[base + (size_t)(q0 + r0) * CDIM + col] =
                __floats2half2_rn(oacc[j][0] * inv_lo, oacc[j][1] * inv_lo);
            *(half2*)&yg[base + (size_t)(q0 + r0 + 8) * CDIM + col] =
                __floats2half2_rn(oacc[j][2] * inv_hi, oacc[j][3] * inv_hi);
        }
    }
#undef LOAD_KV
}

// ---------------------------------------------------------------------------
// PDL launches for the dependent chain.
// ---------------------------------------------------------------------------
template <typename K, typename... Args>
static void launch_pdl(K kernel, dim3 grid, dim3 block, size_t smem, Args... args)
{
    cudaLaunchConfig_t cfg = {};
    cfg.gridDim = grid;
    cfg.blockDim = block;
    cfg.dynamicSmemBytes = smem;
    cudaLaunchAttribute attr[1];
    attr[0].id = cudaLaunchAttributeProgrammaticStreamSerialization;
    attr[0].val.programmaticStreamSerializationAllowed = 1;
    cfg.attrs = attr;
    cfg.numAttrs = 1;
    cudaLaunchKernelEx(&cfg, kernel, args...);
}

extern "C" void kernel_launch(void* const* d_in, const int* in_sizes, int n_in,
                              void* d_out, int out_size)
{
    const float* x  = (const float*)d_in[0];
    const float* Wq = (const float*)d_in[1];
    const float* bq = (const float*)d_in[2];
    const float* Wk = (const float*)d_in[3];
    const float* bk = (const float*)d_in[4];
    const float* Wv = (const float*)d_in[5];
    const float* bv = (const float*)d_in[6];
    const float* Wo = (const float*)d_in[7];
    const float* bo = (const float*)d_in[8];
    float* out = (float*)d_out;
    (void)in_sizes; (void)n_in; (void)out_size;

    __half *qp, *kp, *vp, *yp, *xhp, *whp;
    cudaGetSymbolAddress((void**)&qp,  g_q);
    cudaGetSymbolAddress((void**)&kp,  g_k);
    cudaGetSymbolAddress((void**)&vp,  g_v);
    cudaGetSymbolAddress((void**)&yp,  g_y);
    cudaGetSymbolAddress((void**)&xhp, g_xh);
    cudaGetSymbolAddress((void**)&whp, g_wh);
    __half* who = whp + 3 * (size_t)CDIM * CDIM;

    cudaFuncSetAttribute(attn_kernel,
                         cudaFuncAttributeMaxDynamicSharedMemorySize, ATT_SMEM_B);
    cudaFuncSetAttribute(gemm_qkv_kernel,
                         cudaFuncAttributeMaxDynamicSharedMemorySize, GEMM_SMEM);
    cudaFuncSetAttribute(gemm_out_kernel,
                         cudaFuncAttributeMaxDynamicSharedMemorySize, GEMM_SMEM);

    const int TOT4 = NX4 + 4 * NW4;
    cvt_all_kernel<<<(TOT4 + 255) / 256, 256>>>(x, Wq, Wk, Wv, Wo, xhp, whp);

    launch_pdl(gemm_qkv_kernel, dim3(24, MROWS / BM), dim3(256), (size_t)GEMM_SMEM,
               (const __half*)xhp, (const __half*)whp, bq, bk, bv, qp, kp, vp);

    launch_pdl(attn_kernel, dim3(TSEQ / QR, NHEAD, BATCH), dim3(256), (size_t)ATT_SMEM_B,
               (const __half*)qp, (const __half*)kp, (const __half*)vp, yp);

    launch_pdl(gemm_out_kernel, dim3(CDIM / BN, MROWS / BM), dim3(256), (size_t)GEMM_SMEM,
               (const __half*)yp, (const __half*)who, bo, out);
}